// round 16
// baseline (speedup 1.0000x reference)
#include <cuda_runtime.h>
#include <cuda_bf16.h>
#include <math.h>

#define N_NODES 131072
#define N_EDGES 524288
#define H_DIM   128
#define K_SEL   (N_NODES / 2)
#define LN_EPS  1e-5f

// ---------------- scratch (static device globals) ----------------
__device__ float    g_B0[(size_t)N_NODES * H_DIM];
__device__ float    g_B1[(size_t)N_NODES * H_DIM];
__device__ float    g_B2[(size_t)N_NODES * H_DIM];
__device__ float    g_B3[(size_t)N_NODES * H_DIM];   // agg_skip
__device__ float    g_score[N_NODES];
__device__ float    g_ts[N_NODES];
__device__ unsigned g_key[N_NODES];
__device__ int      g_mapm[N_NODES];     // >=0: compact index, -1 otherwise
__device__ int      g_perm[K_SEL];       // compact index -> original node
__device__ unsigned g_hist[256];
__device__ unsigned g_prefix;
__device__ unsigned g_rem;
__device__ int      g_cnt;
__device__ unsigned g_blkeq[256];
__device__ unsigned g_blkoff[256];
__device__ float    g_invnorm;
// CSR of symmetrized graph
__device__ int      g_deg[N_NODES];
__device__ int      g_rowptr[N_NODES + 1];
__device__ int      g_cur[N_NODES];
__device__ int      g_adj[2 * N_EDGES];
__device__ int      g_tmpscan[N_NODES];
__device__ int      g_bsum[256];

// ---------------- helpers ----------------
__device__ __forceinline__ unsigned sortable_key(float f) {
    unsigned u = __float_as_uint(f);
    return (u & 0x80000000u) ? ~u : (u | 0x80000000u);
}
__device__ __forceinline__ float gelu_exact(float x) { return x * normcdff(x); }
__device__ __forceinline__ unsigned to_tf32(float f) {
    unsigned u;
    asm("cvt.rna.tf32.f32 %0, %1;" : "=r"(u) : "f"(f));
    return u;
}
// L2 evict-last vector load via createpolicy + cache_hint
__device__ __forceinline__ float4 ldg_el(const float* p) {
    float4 v;
    asm volatile(
        "{\n\t"
        ".reg .b64 pol;\n\t"
        "createpolicy.fractional.L2::evict_last.b64 pol, 1.0;\n\t"
        "ld.global.nc.L2::cache_hint.v4.f32 {%0,%1,%2,%3}, [%4], pol;\n\t"
        "}"
        : "=f"(v.x), "=f"(v.y), "=f"(v.z), "=f"(v.w) : "l"(p));
    return v;
}

// ---------------- pool_p norm ----------------
__global__ void k_norm(const float* __restrict__ p) {
    __shared__ float s[128];
    int t = threadIdx.x;
    float v = p[t];
    s[t] = v * v;
    __syncthreads();
    for (int off = 64; off > 0; off >>= 1) {
        if (t < off) s[t] += s[t + off];
        __syncthreads();
    }
    if (t == 0) g_invnorm = rsqrtf(s[0]);
}

// ---------------- scores + keys (warp per row) ----------------
__global__ void k_score(const float* __restrict__ x, const float* __restrict__ p) {
    int row  = blockIdx.x * 4 + (threadIdx.x >> 5);
    int lane = threadIdx.x & 31;
    int c = lane * 4;
    float4 xv = *(const float4*)(x + (size_t)row * H_DIM + c);
    float4 pv = *(const float4*)(p + c);
    float v = xv.x * pv.x + xv.y * pv.y + xv.z * pv.z + xv.w * pv.w;
    #pragma unroll
    for (int off = 16; off > 0; off >>= 1) v += __shfl_xor_sync(0xffffffffu, v, off);
    if (lane == 0) {
        float s = v * g_invnorm;
        g_score[row] = s;
        g_ts[row] = tanhf(s);
        g_key[row] = sortable_key(s);
    }
}

// ---------------- radix select of k-th largest key ----------------
__global__ void k_rinit() {
    int t = threadIdx.x;
    g_hist[t] = 0;
    if (t == 0) { g_prefix = 0; g_rem = K_SEL; g_cnt = 0; }
}
__global__ void k_hist(int shift) {
    __shared__ unsigned h[256];
    int t = threadIdx.x;
    h[t] = 0;
    __syncthreads();
    unsigned pref = g_prefix;
    unsigned hi = (shift == 24) ? 0u : (0xFFFFFFFFu << (shift + 8));
    for (int i = blockIdx.x * blockDim.x + t; i < N_NODES; i += gridDim.x * blockDim.x) {
        unsigned u = g_key[i];
        if ((u & hi) == pref) atomicAdd(&h[(u >> shift) & 255u], 1u);
    }
    __syncthreads();
    if (h[t]) atomicAdd(&g_hist[t], h[t]);
}
__global__ void k_rselect(int shift) {
    unsigned rem = g_rem, pref = g_prefix;
    for (int b = 255; b >= 0; b--) {
        unsigned c = g_hist[b];
        if (c < rem) rem -= c;
        else { pref |= ((unsigned)b) << shift; break; }
    }
    g_prefix = pref;
    g_rem = rem;
    for (int i = 0; i < 256; i++) g_hist[i] = 0;
}

// ---------------- tie-aware selection ----------------
__global__ void k_eqcount() {
    __shared__ unsigned cnt;
    int t = threadIdx.x;
    if (t == 0) cnt = 0;
    __syncthreads();
    int i = blockIdx.x * 512 + t;
    if (g_key[i] == g_prefix) atomicAdd(&cnt, 1u);
    __syncthreads();
    if (t == 0) g_blkeq[blockIdx.x] = cnt;
}
__global__ void k_eqscan() {
    unsigned run = 0;
    for (int i = 0; i < 256; i++) { g_blkoff[i] = run; run += g_blkeq[i]; }
}
__global__ void k_mark() {
    __shared__ int sb[512];
    int t = threadIdx.x;
    int i = blockIdx.x * 512 + t;
    unsigned T = g_prefix;
    unsigned u = g_key[i];
    int eq = (u == T) ? 1 : 0;
    int gt = (u > T) ? 1 : 0;
    sb[t] = eq;
    __syncthreads();
    for (int off = 1; off < 512; off <<= 1) {
        int v = (t >= off) ? sb[t - off] : 0;
        __syncthreads();
        sb[t] += v;
        __syncthreads();
    }
    int excl = sb[t] - eq;
    int sel = gt || (eq && (g_blkoff[blockIdx.x] + (unsigned)excl) < g_rem);
    if (sel) {
        int idx = atomicAdd(&g_cnt, 1);
        g_mapm[i] = idx;
        g_perm[idx] = i;
    } else {
        g_mapm[i] = -1;
    }
}

// ---------------- CSR build ----------------
__global__ void k_count(const int* __restrict__ senders, const int* __restrict__ receivers) {
    for (int e = blockIdx.x * blockDim.x + threadIdx.x; e < N_EDGES; e += gridDim.x * blockDim.x) {
        atomicAdd(&g_deg[senders[e]], 1);
        atomicAdd(&g_deg[receivers[e]], 1);
    }
}
__global__ void k_scan1() {
    __shared__ int sb[512];
    int t = threadIdx.x;
    int i = blockIdx.x * 512 + t;
    int v = g_deg[i];
    sb[t] = v;
    __syncthreads();
    for (int off = 1; off < 512; off <<= 1) {
        int a = (t >= off) ? sb[t - off] : 0;
        __syncthreads();
        sb[t] += a;
        __syncthreads();
    }
    g_tmpscan[i] = sb[t];
    if (t == 511) g_bsum[blockIdx.x] = sb[511];
}
__global__ void k_scan2() {
    __shared__ int sb[256];
    int t = threadIdx.x;
    sb[t] = g_bsum[t];
    __syncthreads();
    for (int off = 1; off < 256; off <<= 1) {
        int a = (t >= off) ? sb[t - off] : 0;
        __syncthreads();
        sb[t] += a;
        __syncthreads();
    }
    g_bsum[t] = sb[t];
}
__global__ void k_scan3() {
    int t = threadIdx.x;
    int i = blockIdx.x * 512 + t;
    int off = (blockIdx.x > 0) ? g_bsum[blockIdx.x - 1] : 0;
    int incl = g_tmpscan[i] + off;
    int excl = incl - g_deg[i];
    g_rowptr[i] = excl;
    g_cur[i] = excl;
    if (i == N_NODES - 1) g_rowptr[N_NODES] = incl;
}
__global__ void k_scatter(const int* __restrict__ senders, const int* __restrict__ receivers) {
    for (int e = blockIdx.x * blockDim.x + threadIdx.x; e < N_EDGES; e += gridDim.x * blockDim.x) {
        int s = senders[e], r = receivers[e];
        g_adj[atomicAdd(&g_cur[s], 1)] = r;
        g_adj[atomicAdd(&g_cur[r], 1)] = s;
    }
}

// ---------------- down aggregation: compact gather ----------------
__global__ void k_down_gather(const float* __restrict__ x, float* __restrict__ out) {
    int r    = blockIdx.x * 8 + (threadIdx.x >> 5);     // compact row
    int lane = threadIdx.x & 31;
    int v = g_perm[r];
    int c = lane * 4;
    int beg = g_rowptr[v], end = g_rowptr[v + 1];
    float4 acc = make_float4(0.f, 0.f, 0.f, 0.f);
    int i = beg;
    for (; i + 4 <= end; i += 4) {
        int u0 = __ldcs(g_adj + i),     u1 = __ldcs(g_adj + i + 1);
        int u2 = __ldcs(g_adj + i + 2), u3 = __ldcs(g_adj + i + 3);
        int m0 = g_mapm[u0], m1 = g_mapm[u1], m2 = g_mapm[u2], m3 = g_mapm[u3];
        float t0 = g_ts[u0], t1 = g_ts[u1], t2 = g_ts[u2], t3 = g_ts[u3];
        float4 x0 = ldg_el(x + (size_t)u0 * H_DIM + c);
        float4 x1 = ldg_el(x + (size_t)u1 * H_DIM + c);
        float4 x2 = ldg_el(x + (size_t)u2 * H_DIM + c);
        float4 x3 = ldg_el(x + (size_t)u3 * H_DIM + c);
        if (m0 >= 0) { acc.x += x0.x * t0; acc.y += x0.y * t0; acc.z += x0.z * t0; acc.w += x0.w * t0; }
        if (m1 >= 0) { acc.x += x1.x * t1; acc.y += x1.y * t1; acc.z += x1.z * t1; acc.w += x1.w * t1; }
        if (m2 >= 0) { acc.x += x2.x * t2; acc.y += x2.y * t2; acc.z += x2.z * t2; acc.w += x2.w * t2; }
        if (m3 >= 0) { acc.x += x3.x * t3; acc.y += x3.y * t3; acc.z += x3.z * t3; acc.w += x3.w * t3; }
    }
    for (; i < end; i++) {
        int u = __ldcs(g_adj + i);
        if (g_mapm[u] >= 0) {
            float t = g_ts[u];
            float4 xv = ldg_el(x + (size_t)u * H_DIM + c);
            acc.x += xv.x * t; acc.y += xv.y * t;
            acc.z += xv.z * t; acc.w += xv.w * t;
        }
    }
    __stcs((float4*)(out + (size_t)r * H_DIM + c), acc);
}

// ---------------- up aggregation split: skip part (x only; no down dependency) ----
__global__ void k_up_skip(const float* __restrict__ x, float* __restrict__ agg_skip) {
    int v    = blockIdx.x * 8 + (threadIdx.x >> 5);
    int lane = threadIdx.x & 31;
    int c = lane * 4;
    int beg = g_rowptr[v], end = g_rowptr[v + 1];
    float4 as = make_float4(0.f, 0.f, 0.f, 0.f);
    int i = beg;
    for (; i + 4 <= end; i += 4) {
        int u0 = __ldcs(g_adj + i),     u1 = __ldcs(g_adj + i + 1);
        int u2 = __ldcs(g_adj + i + 2), u3 = __ldcs(g_adj + i + 3);
        float4 x0 = ldg_el(x + (size_t)u0 * H_DIM + c);
        float4 x1 = ldg_el(x + (size_t)u1 * H_DIM + c);
        float4 x2 = ldg_el(x + (size_t)u2 * H_DIM + c);
        float4 x3 = ldg_el(x + (size_t)u3 * H_DIM + c);
        as.x += x0.x + x1.x + x2.x + x3.x;
        as.y += x0.y + x1.y + x2.y + x3.y;
        as.z += x0.z + x1.z + x2.z + x3.z;
        as.w += x0.w + x1.w + x2.w + x3.w;
    }
    for (; i < end; i++) {
        int u = __ldcs(g_adj + i);
        float4 xv = ldg_el(x + (size_t)u * H_DIM + c);
        as.x += xv.x; as.y += xv.y; as.z += xv.z; as.w += xv.w;
    }
    __stcs((float4*)(agg_skip + (size_t)v * H_DIM + c), as);
}

// ---------------- up aggregation split: recovered part (xd only) ----------------
__global__ void k_up_rec(const float* __restrict__ xd, float* __restrict__ agg_rec) {
    int v    = blockIdx.x * 8 + (threadIdx.x >> 5);
    int lane = threadIdx.x & 31;
    int c = lane * 4;
    int beg = g_rowptr[v], end = g_rowptr[v + 1];
    float4 ar = make_float4(0.f, 0.f, 0.f, 0.f);
    int i = beg;
    for (; i + 4 <= end; i += 4) {
        int u0 = __ldcs(g_adj + i),     u1 = __ldcs(g_adj + i + 1);
        int u2 = __ldcs(g_adj + i + 2), u3 = __ldcs(g_adj + i + 3);
        int m0 = g_mapm[u0], m1 = g_mapm[u1], m2 = g_mapm[u2], m3 = g_mapm[u3];
        if (m0 >= 0) { float4 d = ldg_el(xd + (size_t)m0 * H_DIM + c);
                       ar.x += d.x; ar.y += d.y; ar.z += d.z; ar.w += d.w; }
        if (m1 >= 0) { float4 d = ldg_el(xd + (size_t)m1 * H_DIM + c);
                       ar.x += d.x; ar.y += d.y; ar.z += d.z; ar.w += d.w; }
        if (m2 >= 0) { float4 d = ldg_el(xd + (size_t)m2 * H_DIM + c);
                       ar.x += d.x; ar.y += d.y; ar.z += d.z; ar.w += d.w; }
        if (m3 >= 0) { float4 d = ldg_el(xd + (size_t)m3 * H_DIM + c);
                       ar.x += d.x; ar.y += d.y; ar.z += d.z; ar.w += d.w; }
    }
    for (; i < end; i++) {
        int u = __ldcs(g_adj + i);
        int mu = g_mapm[u];
        if (mu >= 0) {
            float4 dv = ldg_el(xd + (size_t)mu * H_DIM + c);
            ar.x += dv.x; ar.y += dv.y; ar.z += dv.z; ar.w += dv.w;
        }
    }
    __stcs((float4*)(agg_rec + (size_t)v * H_DIM + c), ar);
}

// ---------------- fused 3-layer MLP (tf32 MMA, gelu-gelu-LN), one kernel per conv ----
// SA=132 (A-frag banks g*4+t conflict-free), SW=136 (B-frag banks t*8+g conflict-free).
#define SA 132
#define SW 136

__device__ __forceinline__ void stage_W(const float* __restrict__ W, unsigned* Ws,
                                        int rows, int tid) {
    for (int i = tid; i < rows * 32; i += 256) {
        int r = i >> 5, c4 = (i & 31) * 4;
        float4 w = *(const float4*)(W + r * 128 + c4);
        uint4 o;
        o.x = to_tf32(w.x); o.y = to_tf32(w.y); o.z = to_tf32(w.z); o.w = to_tf32(w.w);
        *(uint4*)(Ws + r * SW + c4) = o;
    }
}
__device__ __forceinline__ void init_bias(float c[16][4], const float* __restrict__ bias, int t) {
    #pragma unroll
    for (int j = 0; j < 16; j++) {
        int col = j * 8 + 2 * t;
        float b0 = __ldg(bias + col), b1 = __ldg(bias + col + 1);
        c[j][0] = b0; c[j][1] = b1; c[j][2] = b0; c[j][3] = b1;
    }
}
__device__ __forceinline__ void mma_128(const unsigned* __restrict__ As,
                                        const unsigned* __restrict__ Wp,
                                        int wm, int g, int t, float c[16][4]) {
    #pragma unroll
    for (int kt = 0; kt < 16; kt++) {
        int k0 = kt * 8;
        unsigned a0 = As[(wm + g)     * SA + k0 + t];
        unsigned a1 = As[(wm + g + 8) * SA + k0 + t];
        unsigned a2 = As[(wm + g)     * SA + k0 + t + 4];
        unsigned a3 = As[(wm + g + 8) * SA + k0 + t + 4];
        #pragma unroll
        for (int j = 0; j < 16; j++) {
            unsigned b0 = Wp[(k0 + t)     * SW + j * 8 + g];
            unsigned b1 = Wp[(k0 + t + 4) * SW + j * 8 + g];
            asm volatile(
                "mma.sync.aligned.m16n8k8.row.col.f32.tf32.tf32.f32 "
                "{%0,%1,%2,%3},{%4,%5,%6,%7},{%8,%9},{%0,%1,%2,%3};"
                : "+f"(c[j][0]), "+f"(c[j][1]), "+f"(c[j][2]), "+f"(c[j][3])
                : "r"(a0), "r"(a1), "r"(a2), "r"(a3), "r"(b0), "r"(b1));
        }
    }
}
// write gelu(c) into As as tf32 (each warp covers its own 16 rows)
__device__ __forceinline__ void gelu_to_smem(float c[16][4], unsigned* As,
                                             int wm, int g, int t) {
    #pragma unroll
    for (int j = 0; j < 16; j++) {
        int col = j * 8 + 2 * t;
        uint2 vA, vB;
        vA.x = to_tf32(gelu_exact(c[j][0])); vA.y = to_tf32(gelu_exact(c[j][1]));
        vB.x = to_tf32(gelu_exact(c[j][2])); vB.y = to_tf32(gelu_exact(c[j][3]));
        *(uint2*)(As + (wm + g)     * SA + col) = vA;
        *(uint2*)(As + (wm + g + 8) * SA + col) = vB;
    }
}

template<bool TWO_IN>
__global__ __launch_bounds__(256) void mma_mlp3(
    const float* __restrict__ A, const float* __restrict__ A2,
    const float* __restrict__ W1, const float* __restrict__ b1,
    const float* __restrict__ W2, const float* __restrict__ b2,
    const float* __restrict__ W3, const float* __restrict__ b3,
    const float* __restrict__ gamma, const float* __restrict__ beta,
    float* __restrict__ out)
{
    extern __shared__ unsigned smu[];
    constexpr int W1ROWS = TWO_IN ? 256 : 128;
    unsigned* Ws = smu;
    unsigned* As = smu + W1ROWS * SW;
    int tid = threadIdx.x;
    int lane = tid & 31, wid = tid >> 5;
    int g = lane >> 2, t = lane & 3;
    int wm = wid * 16;
    size_t rowBase = (size_t)blockIdx.x * 128;

    // ---- layer 1 ----
    stage_W(W1, Ws, W1ROWS, tid);
    for (int i = tid; i < 128 * 32; i += 256) {
        int r = i >> 5, c4 = (i & 31) * 4;
        float4 a = __ldcs((const float4*)(A + (rowBase + r) * 128 + c4));
        uint4 o;
        o.x = to_tf32(a.x); o.y = to_tf32(a.y); o.z = to_tf32(a.z); o.w = to_tf32(a.w);
        *(uint4*)(As + r * SA + c4) = o;
    }
    __syncthreads();

    float c[16][4];
    init_bias(c, b1, t);
    mma_128(As, Ws, wm, g, t, c);
    if (TWO_IN) {
        __syncthreads();
        for (int i = tid; i < 128 * 32; i += 256) {
            int r = i >> 5, c4 = (i & 31) * 4;
            float4 a = __ldcs((const float4*)(A2 + (rowBase + r) * 128 + c4));
            uint4 o;
            o.x = to_tf32(a.x); o.y = to_tf32(a.y); o.z = to_tf32(a.z); o.w = to_tf32(a.w);
            *(uint4*)(As + r * SA + c4) = o;
        }
        __syncthreads();
        mma_128(As, Ws + 128 * SW, wm, g, t, c);
    }

    // ---- layer 2 ----
    __syncthreads();                       // everyone done reading As/Ws
    gelu_to_smem(c, As, wm, g, t);
    stage_W(W2, Ws, 128, tid);
    __syncthreads();
    init_bias(c, b2, t);
    mma_128(As, Ws, wm, g, t, c);

    // ---- layer 3 ----
    __syncthreads();
    gelu_to_smem(c, As, wm, g, t);
    stage_W(W3, Ws, 128, tid);
    __syncthreads();
    init_bias(c, b3, t);
    mma_128(As, Ws, wm, g, t, c);

    // ---- LayerNorm epilogue + write out ----
    float s1a = 0.f, s2a = 0.f, s1b = 0.f, s2b = 0.f;
    #pragma unroll
    for (int j = 0; j < 16; j++) {
        s1a += c[j][0] + c[j][1];
        s2a += c[j][0] * c[j][0] + c[j][1] * c[j][1];
        s1b += c[j][2] + c[j][3];
        s2b += c[j][2] * c[j][2] + c[j][3] * c[j][3];
    }
    #pragma unroll
    for (int off = 1; off <= 2; off <<= 1) {
        s1a += __shfl_xor_sync(0xffffffffu, s1a, off);
        s2a += __shfl_xor_sync(0xffffffffu, s2a, off);
        s1b += __shfl_xor_sync(0xffffffffu, s1b, off);
        s2b += __shfl_xor_sync(0xffffffffu, s2b, off);
    }
    float muA = s1a * (1.0f / 128.0f);
    float muB = s1b * (1.0f / 128.0f);
    float rsA = rsqrtf(s2a * (1.0f / 128.0f) - muA * muA + LN_EPS);
    float rsB = rsqrtf(s2b * (1.0f / 128.0f) - muB * muB + LN_EPS);
    size_t rA = rowBase + wm + g;
    size_t rB = rA + 8;
    #pragma unroll
    for (int j = 0; j < 16; j++) {
        int col = j * 8 + 2 * t;
        float g0 = __ldg(gamma + col), g1 = __ldg(gamma + col + 1);
        float be0 = __ldg(beta + col), be1 = __ldg(beta + col + 1);
        float2 oA = make_float2((c[j][0] - muA) * rsA * g0 + be0,
                                (c[j][1] - muA) * rsA * g1 + be1);
        float2 oB = make_float2((c[j][2] - muB) * rsB * g0 + be0,
                                (c[j][3] - muB) * rsB * g1 + be1);
        *(float2*)(out + rA * 128 + col) = oA;   // normal store: xd stays L2-resident
        *(float2*)(out + rB * 128 + col) = oB;
    }
}

#define SMEM_1IN ((128 * SW + 128 * SA) * 4)
#define SMEM_2IN ((256 * SW + 128 * SA) * 4)

// ---------------- launch ----------------
extern "C" void kernel_launch(void* const* d_in, const int* in_sizes, int n_in,
                              void* d_out, int out_size) {
    const float* x      = (const float*)d_in[0];
    const int*   ei     = (const int*)d_in[1];
    const float* pool_p = (const float*)d_in[2];
    const float* dW1 = (const float*)d_in[3];
    const float* db1 = (const float*)d_in[4];
    const float* dW2 = (const float*)d_in[5];
    const float* db2 = (const float*)d_in[6];
    const float* dW3 = (const float*)d_in[7];
    const float* db3 = (const float*)d_in[8];
    const float* dg    = (const float*)d_in[9];
    const float* dbeta = (const float*)d_in[10];
    const float* uW1 = (const float*)d_in[11];
    const float* ub1 = (const float*)d_in[12];
    const float* uW2 = (const float*)d_in[13];
    const float* ub2 = (const float*)d_in[14];
    const float* uW3 = (const float*)d_in[15];
    const float* ub3 = (const float*)d_in[16];
    const float* ug    = (const float*)d_in[17];
    const float* ubeta = (const float*)d_in[18];
    float* out = (float*)d_out;

    const int* senders   = ei;
    const int* receivers = ei + N_EDGES;

    float *B0, *B1, *B3;
    cudaGetSymbolAddress((void**)&B0, g_B0);
    cudaGetSymbolAddress((void**)&B1, g_B1);
    cudaGetSymbolAddress((void**)&B3, g_B3);
    int* degp;
    cudaGetSymbolAddress((void**)&degp, g_deg);

    cudaFuncSetAttribute(mma_mlp3<false>, cudaFuncAttributeMaxDynamicSharedMemorySize, SMEM_1IN);
    cudaFuncSetAttribute(mma_mlp3<true >, cudaFuncAttributeMaxDynamicSharedMemorySize, SMEM_2IN);

    // side stream + events (created once)
    static cudaStream_t s1 = nullptr;
    static cudaEvent_t eFork = nullptr, eCsr = nullptr, eSkip = nullptr;
    if (!s1) {
        cudaStreamCreateWithFlags(&s1, cudaStreamNonBlocking);
        cudaEventCreateWithFlags(&eFork, cudaEventDisableTiming);
        cudaEventCreateWithFlags(&eCsr,  cudaEventDisableTiming);
        cudaEventCreateWithFlags(&eSkip, cudaEventDisableTiming);
    }

    // ---- fork side stream ----
    cudaEventRecord(eFork, 0);
    cudaStreamWaitEvent(s1, eFork, 0);

    // ---- side stream: CSR build, then up-skip aggregation ----
    cudaMemsetAsync(degp, 0, N_NODES * sizeof(int), s1);
    k_count<<<2048, 256, 0, s1>>>(senders, receivers);
    k_scan1<<<256, 512, 0, s1>>>();
    k_scan2<<<1, 256, 0, s1>>>();
    k_scan3<<<256, 512, 0, s1>>>();
    k_scatter<<<2048, 256, 0, s1>>>(senders, receivers);
    cudaEventRecord(eCsr, s1);
    k_up_skip<<<N_NODES / 8, 256, 0, s1>>>(x, B3);
    cudaEventRecord(eSkip, s1);

    // ---- main stream: pooling scores + exact top-k selection ----
    k_norm<<<1, 128>>>(pool_p);
    k_score<<<N_NODES / 4, 128>>>(x, pool_p);
    k_rinit<<<1, 256>>>();
    for (int sh = 24; sh >= 0; sh -= 8) {
        k_hist<<<256, 256>>>(sh);
        k_rselect<<<1, 1>>>(sh);
    }
    k_eqcount<<<256, 512>>>();
    k_eqscan<<<1, 1>>>();
    k_mark<<<256, 512>>>();

    // ---- join: down conv = gather + ONE fused MLP kernel ----
    cudaStreamWaitEvent(0, eCsr, 0);
    k_down_gather<<<K_SEL / 8, 256>>>(x, B1);
    mma_mlp3<false><<<K_SEL / 128, 256, SMEM_1IN>>>(
        B1, nullptr, dW1, db1, dW2, db2, dW3, db3, dg, dbeta, B0);   // xd -> B0

    // ---- up conv: recovered aggregation + ONE fused MLP kernel ----
    k_up_rec<<<N_NODES / 8, 256>>>(B0, B1);              // agg_rec -> B1
    cudaStreamWaitEvent(0, eSkip, 0);
    mma_mlp3<true><<<N_NODES / 128, 256, SMEM_2IN>>>(
        B1, B3, uW1, ub1, uW2, ub2, uW3, ub3, ug, ubeta, out);
}

// round 17
// speedup vs baseline: 1.0289x; 1.0289x over previous
#include <cuda_runtime.h>
#include <cuda_bf16.h>
#include <cuda_fp16.h>
#include <math.h>

#define N_NODES 131072
#define N_EDGES 524288
#define H_DIM   128
#define K_SEL   (N_NODES / 2)
#define LN_EPS  1e-5f

// ---------------- scratch (static device globals) ----------------
__device__ float    g_B0[(size_t)N_NODES * H_DIM];
__device__ float    g_B1[(size_t)N_NODES * H_DIM];
__device__ float    g_B2[(size_t)N_NODES * H_DIM];
__device__ float    g_B3[(size_t)N_NODES * H_DIM];   // agg_skip
__device__ __half   g_xh[(size_t)N_NODES * H_DIM];   // fp16 mirror of x for gathers
__device__ float    g_score[N_NODES];
__device__ float    g_ts[N_NODES];
__device__ unsigned g_key[N_NODES];
__device__ int      g_mapm[N_NODES];     // >=0: compact index, -1 otherwise
__device__ int      g_perm[K_SEL];       // compact index -> original node
__device__ unsigned g_hist[256];
__device__ unsigned g_prefix;
__device__ unsigned g_rem;
__device__ int      g_cnt;
__device__ unsigned g_blkeq[256];
__device__ unsigned g_blkoff[256];
__device__ float    g_invnorm;
// CSR of symmetrized graph
__device__ int      g_deg[N_NODES];
__device__ int      g_rowptr[N_NODES + 1];
__device__ int      g_cur[N_NODES];
__device__ int      g_adj[2 * N_EDGES];
__device__ int      g_tmpscan[N_NODES];
__device__ int      g_bsum[256];

// ---------------- helpers ----------------
__device__ __forceinline__ unsigned sortable_key(float f) {
    unsigned u = __float_as_uint(f);
    return (u & 0x80000000u) ? ~u : (u | 0x80000000u);
}
__device__ __forceinline__ float gelu_exact(float x) { return x * normcdff(x); }
__device__ __forceinline__ unsigned to_tf32(float f) {
    unsigned u;
    asm("cvt.rna.tf32.f32 %0, %1;" : "=r"(u) : "f"(f));
    return u;
}
// L2 evict-last vector load via createpolicy + cache_hint
__device__ __forceinline__ float4 ldg_el(const float* p) {
    float4 v;
    asm volatile(
        "{\n\t"
        ".reg .b64 pol;\n\t"
        "createpolicy.fractional.L2::evict_last.b64 pol, 1.0;\n\t"
        "ld.global.nc.L2::cache_hint.v4.f32 {%0,%1,%2,%3}, [%4], pol;\n\t"
        "}"
        : "=f"(v.x), "=f"(v.y), "=f"(v.z), "=f"(v.w) : "l"(p));
    return v;
}
// unpack 4 halves (uint2) to float4
__device__ __forceinline__ float4 h4_to_f4(uint2 raw) {
    __half2 a = *reinterpret_cast<__half2*>(&raw.x);
    __half2 b = *reinterpret_cast<__half2*>(&raw.y);
    float2 fa = __half22float2(a), fb = __half22float2(b);
    return make_float4(fa.x, fa.y, fb.x, fb.y);
}

// ---------------- x -> fp16 mirror ----------------
__global__ void k_tohalf(const float* __restrict__ x, __half* __restrict__ xh) {
    int n4 = N_NODES * H_DIM / 4;
    for (int i = blockIdx.x * blockDim.x + threadIdx.x; i < n4; i += gridDim.x * blockDim.x) {
        float4 v = __ldcs((const float4*)(x) + i);
        __half2 a = __floats2half2_rn(v.x, v.y);
        __half2 b = __floats2half2_rn(v.z, v.w);
        uint2 o;
        o.x = *reinterpret_cast<unsigned*>(&a);
        o.y = *reinterpret_cast<unsigned*>(&b);
        *((uint2*)(xh) + i) = o;
    }
}

// ---------------- pool_p norm ----------------
__global__ void k_norm(const float* __restrict__ p) {
    __shared__ float s[128];
    int t = threadIdx.x;
    float v = p[t];
    s[t] = v * v;
    __syncthreads();
    for (int off = 64; off > 0; off >>= 1) {
        if (t < off) s[t] += s[t + off];
        __syncthreads();
    }
    if (t == 0) g_invnorm = rsqrtf(s[0]);
}

// ---------------- scores + keys (warp per row) ----------------
__global__ void k_score(const float* __restrict__ x, const float* __restrict__ p) {
    int row  = blockIdx.x * 4 + (threadIdx.x >> 5);
    int lane = threadIdx.x & 31;
    int c = lane * 4;
    float4 xv = *(const float4*)(x + (size_t)row * H_DIM + c);
    float4 pv = *(const float4*)(p + c);
    float v = xv.x * pv.x + xv.y * pv.y + xv.z * pv.z + xv.w * pv.w;
    #pragma unroll
    for (int off = 16; off > 0; off >>= 1) v += __shfl_xor_sync(0xffffffffu, v, off);
    if (lane == 0) {
        float s = v * g_invnorm;
        g_score[row] = s;
        g_ts[row] = tanhf(s);
        g_key[row] = sortable_key(s);
    }
}

// ---------------- radix select of k-th largest key ----------------
__global__ void k_rinit() {
    int t = threadIdx.x;
    g_hist[t] = 0;
    if (t == 0) { g_prefix = 0; g_rem = K_SEL; g_cnt = 0; }
}
__global__ void k_hist(int shift) {
    __shared__ unsigned h[256];
    int t = threadIdx.x;
    h[t] = 0;
    __syncthreads();
    unsigned pref = g_prefix;
    unsigned hi = (shift == 24) ? 0u : (0xFFFFFFFFu << (shift + 8));
    for (int i = blockIdx.x * blockDim.x + t; i < N_NODES; i += gridDim.x * blockDim.x) {
        unsigned u = g_key[i];
        if ((u & hi) == pref) atomicAdd(&h[(u >> shift) & 255u], 1u);
    }
    __syncthreads();
    if (h[t]) atomicAdd(&g_hist[t], h[t]);
}
__global__ void k_rselect(int shift) {
    unsigned rem = g_rem, pref = g_prefix;
    for (int b = 255; b >= 0; b--) {
        unsigned c = g_hist[b];
        if (c < rem) rem -= c;
        else { pref |= ((unsigned)b) << shift; break; }
    }
    g_prefix = pref;
    g_rem = rem;
    for (int i = 0; i < 256; i++) g_hist[i] = 0;
}

// ---------------- tie-aware selection ----------------
__global__ void k_eqcount() {
    __shared__ unsigned cnt;
    int t = threadIdx.x;
    if (t == 0) cnt = 0;
    __syncthreads();
    int i = blockIdx.x * 512 + t;
    if (g_key[i] == g_prefix) atomicAdd(&cnt, 1u);
    __syncthreads();
    if (t == 0) g_blkeq[blockIdx.x] = cnt;
}
__global__ void k_eqscan() {
    unsigned run = 0;
    for (int i = 0; i < 256; i++) { g_blkoff[i] = run; run += g_blkeq[i]; }
}
__global__ void k_mark() {
    __shared__ int sb[512];
    int t = threadIdx.x;
    int i = blockIdx.x * 512 + t;
    unsigned T = g_prefix;
    unsigned u = g_key[i];
    int eq = (u == T) ? 1 : 0;
    int gt = (u > T) ? 1 : 0;
    sb[t] = eq;
    __syncthreads();
    for (int off = 1; off < 512; off <<= 1) {
        int v = (t >= off) ? sb[t - off] : 0;
        __syncthreads();
        sb[t] += v;
        __syncthreads();
    }
    int excl = sb[t] - eq;
    int sel = gt || (eq && (g_blkoff[blockIdx.x] + (unsigned)excl) < g_rem);
    if (sel) {
        int idx = atomicAdd(&g_cnt, 1);
        g_mapm[i] = idx;
        g_perm[idx] = i;
    } else {
        g_mapm[i] = -1;
    }
}

// ---------------- CSR build ----------------
__global__ void k_count(const int* __restrict__ senders, const int* __restrict__ receivers) {
    for (int e = blockIdx.x * blockDim.x + threadIdx.x; e < N_EDGES; e += gridDim.x * blockDim.x) {
        atomicAdd(&g_deg[senders[e]], 1);
        atomicAdd(&g_deg[receivers[e]], 1);
    }
}
__global__ void k_scan1() {
    __shared__ int sb[512];
    int t = threadIdx.x;
    int i = blockIdx.x * 512 + t;
    int v = g_deg[i];
    sb[t] = v;
    __syncthreads();
    for (int off = 1; off < 512; off <<= 1) {
        int a = (t >= off) ? sb[t - off] : 0;
        __syncthreads();
        sb[t] += a;
        __syncthreads();
    }
    g_tmpscan[i] = sb[t];
    if (t == 511) g_bsum[blockIdx.x] = sb[511];
}
__global__ void k_scan2() {
    __shared__ int sb[256];
    int t = threadIdx.x;
    sb[t] = g_bsum[t];
    __syncthreads();
    for (int off = 1; off < 256; off <<= 1) {
        int a = (t >= off) ? sb[t - off] : 0;
        __syncthreads();
        sb[t] += a;
        __syncthreads();
    }
    g_bsum[t] = sb[t];
}
__global__ void k_scan3() {
    int t = threadIdx.x;
    int i = blockIdx.x * 512 + t;
    int off = (blockIdx.x > 0) ? g_bsum[blockIdx.x - 1] : 0;
    int incl = g_tmpscan[i] + off;
    int excl = incl - g_deg[i];
    g_rowptr[i] = excl;
    g_cur[i] = excl;
    if (i == N_NODES - 1) g_rowptr[N_NODES] = incl;
}
__global__ void k_scatter(const int* __restrict__ senders, const int* __restrict__ receivers) {
    for (int e = blockIdx.x * blockDim.x + threadIdx.x; e < N_EDGES; e += gridDim.x * blockDim.x) {
        int s = senders[e], r = receivers[e];
        g_adj[atomicAdd(&g_cur[s], 1)] = r;
        g_adj[atomicAdd(&g_cur[r], 1)] = s;
    }
}

// ---------------- down aggregation: compact gather (fp16 x, conditional loads) ----
__global__ void k_down_gather(const __half* __restrict__ xh, float* __restrict__ out) {
    int r    = blockIdx.x * 8 + (threadIdx.x >> 5);     // compact row
    int lane = threadIdx.x & 31;
    int v = g_perm[r];
    int c = lane * 4;
    int beg = g_rowptr[v], end = g_rowptr[v + 1];
    float4 acc = make_float4(0.f, 0.f, 0.f, 0.f);
    int i = beg;
    for (; i + 4 <= end; i += 4) {
        int u0 = __ldcs(g_adj + i),     u1 = __ldcs(g_adj + i + 1);
        int u2 = __ldcs(g_adj + i + 2), u3 = __ldcs(g_adj + i + 3);
        int m0 = g_mapm[u0], m1 = g_mapm[u1], m2 = g_mapm[u2], m3 = g_mapm[u3];
        if (m0 >= 0) {
            float t0 = g_ts[u0];
            float4 xv = h4_to_f4(__ldg((const uint2*)(xh + (size_t)u0 * H_DIM + c)));
            acc.x += xv.x * t0; acc.y += xv.y * t0; acc.z += xv.z * t0; acc.w += xv.w * t0;
        }
        if (m1 >= 0) {
            float t1 = g_ts[u1];
            float4 xv = h4_to_f4(__ldg((const uint2*)(xh + (size_t)u1 * H_DIM + c)));
            acc.x += xv.x * t1; acc.y += xv.y * t1; acc.z += xv.z * t1; acc.w += xv.w * t1;
        }
        if (m2 >= 0) {
            float t2 = g_ts[u2];
            float4 xv = h4_to_f4(__ldg((const uint2*)(xh + (size_t)u2 * H_DIM + c)));
            acc.x += xv.x * t2; acc.y += xv.y * t2; acc.z += xv.z * t2; acc.w += xv.w * t2;
        }
        if (m3 >= 0) {
            float t3 = g_ts[u3];
            float4 xv = h4_to_f4(__ldg((const uint2*)(xh + (size_t)u3 * H_DIM + c)));
            acc.x += xv.x * t3; acc.y += xv.y * t3; acc.z += xv.z * t3; acc.w += xv.w * t3;
        }
    }
    for (; i < end; i++) {
        int u = __ldcs(g_adj + i);
        if (g_mapm[u] >= 0) {
            float t = g_ts[u];
            float4 xv = h4_to_f4(__ldg((const uint2*)(xh + (size_t)u * H_DIM + c)));
            acc.x += xv.x * t; acc.y += xv.y * t;
            acc.z += xv.z * t; acc.w += xv.w * t;
        }
    }
    __stcs((float4*)(out + (size_t)r * H_DIM + c), acc);
}

// ---------------- up aggregation split: skip part (fp16 x) ----------------
__global__ void k_up_skip(const __half* __restrict__ xh, float* __restrict__ agg_skip) {
    int v    = blockIdx.x * 8 + (threadIdx.x >> 5);
    int lane = threadIdx.x & 31;
    int c = lane * 4;
    int beg = g_rowptr[v], end = g_rowptr[v + 1];
    float4 as = make_float4(0.f, 0.f, 0.f, 0.f);
    int i = beg;
    for (; i + 4 <= end; i += 4) {
        int u0 = __ldcs(g_adj + i),     u1 = __ldcs(g_adj + i + 1);
        int u2 = __ldcs(g_adj + i + 2), u3 = __ldcs(g_adj + i + 3);
        float4 x0 = h4_to_f4(__ldg((const uint2*)(xh + (size_t)u0 * H_DIM + c)));
        float4 x1 = h4_to_f4(__ldg((const uint2*)(xh + (size_t)u1 * H_DIM + c)));
        float4 x2 = h4_to_f4(__ldg((const uint2*)(xh + (size_t)u2 * H_DIM + c)));
        float4 x3 = h4_to_f4(__ldg((const uint2*)(xh + (size_t)u3 * H_DIM + c)));
        as.x += x0.x + x1.x + x2.x + x3.x;
        as.y += x0.y + x1.y + x2.y + x3.y;
        as.z += x0.z + x1.z + x2.z + x3.z;
        as.w += x0.w + x1.w + x2.w + x3.w;
    }
    for (; i < end; i++) {
        int u = __ldcs(g_adj + i);
        float4 xv = h4_to_f4(__ldg((const uint2*)(xh + (size_t)u * H_DIM + c)));
        as.x += xv.x; as.y += xv.y; as.z += xv.z; as.w += xv.w;
    }
    __stcs((float4*)(agg_skip + (size_t)v * H_DIM + c), as);
}

// ---------------- up aggregation split: recovered part (fp32 xd, conditional) ------
__global__ void k_up_rec(const float* __restrict__ xd, float* __restrict__ agg_rec) {
    int v    = blockIdx.x * 8 + (threadIdx.x >> 5);
    int lane = threadIdx.x & 31;
    int c = lane * 4;
    int beg = g_rowptr[v], end = g_rowptr[v + 1];
    float4 ar = make_float4(0.f, 0.f, 0.f, 0.f);
    int i = beg;
    for (; i + 4 <= end; i += 4) {
        int u0 = __ldcs(g_adj + i),     u1 = __ldcs(g_adj + i + 1);
        int u2 = __ldcs(g_adj + i + 2), u3 = __ldcs(g_adj + i + 3);
        int m0 = g_mapm[u0], m1 = g_mapm[u1], m2 = g_mapm[u2], m3 = g_mapm[u3];
        if (m0 >= 0) { float4 d = ldg_el(xd + (size_t)m0 * H_DIM + c);
                       ar.x += d.x; ar.y += d.y; ar.z += d.z; ar.w += d.w; }
        if (m1 >= 0) { float4 d = ldg_el(xd + (size_t)m1 * H_DIM + c);
                       ar.x += d.x; ar.y += d.y; ar.z += d.z; ar.w += d.w; }
        if (m2 >= 0) { float4 d = ldg_el(xd + (size_t)m2 * H_DIM + c);
                       ar.x += d.x; ar.y += d.y; ar.z += d.z; ar.w += d.w; }
        if (m3 >= 0) { float4 d = ldg_el(xd + (size_t)m3 * H_DIM + c);
                       ar.x += d.x; ar.y += d.y; ar.z += d.z; ar.w += d.w; }
    }
    for (; i < end; i++) {
        int u = __ldcs(g_adj + i);
        int mu = g_mapm[u];
        if (mu >= 0) {
            float4 dv = ldg_el(xd + (size_t)mu * H_DIM + c);
            ar.x += dv.x; ar.y += dv.y; ar.z += dv.z; ar.w += dv.w;
        }
    }
    __stcs((float4*)(agg_rec + (size_t)v * H_DIM + c), ar);
}

// ---------------- tf32 tensor-core GEMM (+bias, +GELU or +LN epilogue) ----------------
// Separate SMEM strides: A uses SA=132, W uses SW=136; both frag patterns conflict-free.
#define SA 132
#define SW 136
template<bool TWO_IN, bool DO_LN>
__global__ __launch_bounds__(256) void mma_gemm(
    const float* __restrict__ A, const float* __restrict__ A2,
    const float* __restrict__ W, const float* __restrict__ bias,
    const float* __restrict__ gamma, const float* __restrict__ beta,
    float* __restrict__ out)
{
    extern __shared__ unsigned smu[];
    constexpr int WROWS = TWO_IN ? 256 : 128;
    unsigned* Ws = smu;
    unsigned* As = smu + WROWS * SW;
    int tid = threadIdx.x;

    for (int i = tid; i < WROWS * 32; i += 256) {
        int r = i >> 5, c4 = (i & 31) * 4;
        float4 w = *(const float4*)(W + r * 128 + c4);
        uint4 o;
        o.x = to_tf32(w.x); o.y = to_tf32(w.y); o.z = to_tf32(w.z); o.w = to_tf32(w.w);
        *(uint4*)(Ws + r * SW + c4) = o;
    }

    int lane = tid & 31, wid = tid >> 5;
    int g = lane >> 2, t = lane & 3;
    int wm = wid * 16;
    size_t rowBase = (size_t)blockIdx.x * 128;

    float c[16][4];
    #pragma unroll
    for (int j = 0; j < 16; j++) {
        int col = j * 8 + 2 * t;
        float b0 = __ldg(bias + col), b1 = __ldg(bias + col + 1);
        c[j][0] = b0; c[j][1] = b1; c[j][2] = b0; c[j][3] = b1;
    }

    #pragma unroll
    for (int pass = 0; pass < (TWO_IN ? 2 : 1); pass++) {
        const float* Ain = pass ? A2 : A;
        const unsigned* Wp = Ws + pass * 128 * SW;
        __syncthreads();
        for (int i = tid; i < 128 * 32; i += 256) {
            int r = i >> 5, c4 = (i & 31) * 4;
            float4 a = __ldcs((const float4*)(Ain + (rowBase + r) * 128 + c4));
            uint4 o;
            o.x = to_tf32(a.x); o.y = to_tf32(a.y); o.z = to_tf32(a.z); o.w = to_tf32(a.w);
            *(uint4*)(As + r * SA + c4) = o;
        }
        __syncthreads();
        #pragma unroll
        for (int kt = 0; kt < 16; kt++) {
            int k0 = kt * 8;
            unsigned a0 = As[(wm + g)     * SA + k0 + t];
            unsigned a1 = As[(wm + g + 8) * SA + k0 + t];
            unsigned a2 = As[(wm + g)     * SA + k0 + t + 4];
            unsigned a3 = As[(wm + g + 8) * SA + k0 + t + 4];
            #pragma unroll
            for (int j = 0; j < 16; j++) {
                unsigned b0 = Wp[(k0 + t)     * SW + j * 8 + g];
                unsigned b1 = Wp[(k0 + t + 4) * SW + j * 8 + g];
                asm volatile(
                    "mma.sync.aligned.m16n8k8.row.col.f32.tf32.tf32.f32 "
                    "{%0,%1,%2,%3},{%4,%5,%6,%7},{%8,%9},{%0,%1,%2,%3};"
                    : "+f"(c[j][0]), "+f"(c[j][1]), "+f"(c[j][2]), "+f"(c[j][3])
                    : "r"(a0), "r"(a1), "r"(a2), "r"(a3), "r"(b0), "r"(b1));
            }
        }
    }

    size_t rA = rowBase + wm + g;
    size_t rB = rA + 8;

    if (!DO_LN) {
        #pragma unroll
        for (int j = 0; j < 16; j++) {
            int col = j * 8 + 2 * t;
            float2 oA = make_float2(gelu_exact(c[j][0]), gelu_exact(c[j][1]));
            float2 oB = make_float2(gelu_exact(c[j][2]), gelu_exact(c[j][3]));
            __stcs((float2*)(out + rA * 128 + col), oA);
            __stcs((float2*)(out + rB * 128 + col), oB);
        }
    } else {
        float s1a = 0.f, s2a = 0.f, s1b = 0.f, s2b = 0.f;
        #pragma unroll
        for (int j = 0; j < 16; j++) {
            s1a += c[j][0] + c[j][1];
            s2a += c[j][0] * c[j][0] + c[j][1] * c[j][1];
            s1b += c[j][2] + c[j][3];
            s2b += c[j][2] * c[j][2] + c[j][3] * c[j][3];
        }
        #pragma unroll
        for (int off = 1; off <= 2; off <<= 1) {
            s1a += __shfl_xor_sync(0xffffffffu, s1a, off);
            s2a += __shfl_xor_sync(0xffffffffu, s2a, off);
            s1b += __shfl_xor_sync(0xffffffffu, s1b, off);
            s2b += __shfl_xor_sync(0xffffffffu, s2b, off);
        }
        float muA = s1a * (1.0f / 128.0f);
        float muB = s1b * (1.0f / 128.0f);
        float rsA = rsqrtf(s2a * (1.0f / 128.0f) - muA * muA + LN_EPS);
        float rsB = rsqrtf(s2b * (1.0f / 128.0f) - muB * muB + LN_EPS);
        #pragma unroll
        for (int j = 0; j < 16; j++) {
            int col = j * 8 + 2 * t;
            float g0 = __ldg(gamma + col), g1 = __ldg(gamma + col + 1);
            float be0 = __ldg(beta + col), be1 = __ldg(beta + col + 1);
            float2 oA = make_float2((c[j][0] - muA) * rsA * g0 + be0,
                                    (c[j][1] - muA) * rsA * g1 + be1);
            float2 oB = make_float2((c[j][2] - muB) * rsB * g0 + be0,
                                    (c[j][3] - muB) * rsB * g1 + be1);
            *(float2*)(out + rA * 128 + col) = oA;   // normal store: keep resident (xd)
            *(float2*)(out + rB * 128 + col) = oB;
        }
    }
}

#define SMEM_1IN ((128 * SW + 128 * SA) * 4)
#define SMEM_2IN ((256 * SW + 128 * SA) * 4)

// ---------------- launch ----------------
extern "C" void kernel_launch(void* const* d_in, const int* in_sizes, int n_in,
                              void* d_out, int out_size) {
    const float* x      = (const float*)d_in[0];
    const int*   ei     = (const int*)d_in[1];
    const float* pool_p = (const float*)d_in[2];
    const float* dW1 = (const float*)d_in[3];
    const float* db1 = (const float*)d_in[4];
    const float* dW2 = (const float*)d_in[5];
    const float* db2 = (const float*)d_in[6];
    const float* dW3 = (const float*)d_in[7];
    const float* db3 = (const float*)d_in[8];
    const float* dg    = (const float*)d_in[9];
    const float* dbeta = (const float*)d_in[10];
    const float* uW1 = (const float*)d_in[11];
    const float* ub1 = (const float*)d_in[12];
    const float* uW2 = (const float*)d_in[13];
    const float* ub2 = (const float*)d_in[14];
    const float* uW3 = (const float*)d_in[15];
    const float* ub3 = (const float*)d_in[16];
    const float* ug    = (const float*)d_in[17];
    const float* ubeta = (const float*)d_in[18];
    float* out = (float*)d_out;

    const int* senders   = ei;
    const int* receivers = ei + N_EDGES;

    float *B0, *B1, *B2, *B3;
    __half* XH;
    cudaGetSymbolAddress((void**)&B0, g_B0);
    cudaGetSymbolAddress((void**)&B1, g_B1);
    cudaGetSymbolAddress((void**)&B2, g_B2);
    cudaGetSymbolAddress((void**)&B3, g_B3);
    cudaGetSymbolAddress((void**)&XH, g_xh);
    int* degp;
    cudaGetSymbolAddress((void**)&degp, g_deg);

    cudaFuncSetAttribute(mma_gemm<false, false>, cudaFuncAttributeMaxDynamicSharedMemorySize, SMEM_1IN);
    cudaFuncSetAttribute(mma_gemm<false, true >, cudaFuncAttributeMaxDynamicSharedMemorySize, SMEM_1IN);
    cudaFuncSetAttribute(mma_gemm<true,  false>, cudaFuncAttributeMaxDynamicSharedMemorySize, SMEM_2IN);

    // side stream + events (created once)
    static cudaStream_t s1 = nullptr;
    static cudaEvent_t eFork = nullptr, eCsr = nullptr, eSkip = nullptr;
    if (!s1) {
        cudaStreamCreateWithFlags(&s1, cudaStreamNonBlocking);
        cudaEventCreateWithFlags(&eFork, cudaEventDisableTiming);
        cudaEventCreateWithFlags(&eCsr,  cudaEventDisableTiming);
        cudaEventCreateWithFlags(&eSkip, cudaEventDisableTiming);
    }

    // ---- fork side stream ----
    cudaEventRecord(eFork, 0);
    cudaStreamWaitEvent(s1, eFork, 0);

    // ---- side stream: fp16 mirror + CSR build + up-skip aggregation ----
    cudaMemsetAsync(degp, 0, N_NODES * sizeof(int), s1);
    k_tohalf<<<2048, 256, 0, s1>>>(x, XH);
    k_count<<<2048, 256, 0, s1>>>(senders, receivers);
    k_scan1<<<256, 512, 0, s1>>>();
    k_scan2<<<1, 256, 0, s1>>>();
    k_scan3<<<256, 512, 0, s1>>>();
    k_scatter<<<2048, 256, 0, s1>>>(senders, receivers);
    cudaEventRecord(eCsr, s1);
    k_up_skip<<<N_NODES / 8, 256, 0, s1>>>(XH, B3);
    cudaEventRecord(eSkip, s1);

    // ---- main stream: pooling scores + exact top-k selection ----
    k_norm<<<1, 128>>>(pool_p);
    k_score<<<N_NODES / 4, 128>>>(x, pool_p);
    k_rinit<<<1, 256>>>();
    for (int sh = 24; sh >= 0; sh -= 8) {
        k_hist<<<256, 256>>>(sh);
        k_rselect<<<1, 1>>>(sh);
    }
    k_eqcount<<<256, 512>>>();
    k_eqscan<<<1, 1>>>();
    k_mark<<<256, 512>>>();

    // ---- join: down conv needs CSR + fp16 mirror + selection ----
    cudaStreamWaitEvent(0, eCsr, 0);
    k_down_gather<<<K_SEL / 8, 256>>>(XH, B1);
    mma_gemm<false, false><<<K_SEL / 128, 256, SMEM_1IN>>>(B1, nullptr, dW1, db1, nullptr, nullptr, B2);
    mma_gemm<false, false><<<K_SEL / 128, 256, SMEM_1IN>>>(B2, nullptr, dW2, db2, nullptr, nullptr, B1);
    mma_gemm<false, true ><<<K_SEL / 128, 256, SMEM_1IN>>>(B1, nullptr, dW3, db3, dg, dbeta, B0); // xd

    // ---- up conv: recovered aggregation, then MLP (waits for agg_skip) ----
    k_up_rec<<<N_NODES / 8, 256>>>(B0, B1);              // agg_rec -> B1
    cudaStreamWaitEvent(0, eSkip, 0);
    mma_gemm<true,  false><<<N_NODES / 128, 256, SMEM_2IN>>>(B1, B3, uW1, ub1, nullptr, nullptr, B2);
    mma_gemm<false, false><<<N_NODES / 128, 256, SMEM_1IN>>>(B2, nullptr, uW2, ub2, nullptr, nullptr, B1);
    mma_gemm<false, true ><<<N_NODES / 128, 256, SMEM_1IN>>>(B1, nullptr, uW3, ub3, ug, ubeta, out);
}